// round 1
// baseline (speedup 1.0000x reference)
#include <cuda_runtime.h>

#define D 128
#define H 4
#define NMAX 50000
#define EMAX 600000

// Scratch (device globals: allocation inside kernel_launch is forbidden)
__device__ float g_Q[(size_t)NMAX * D];
__device__ float g_K[(size_t)NMAX * D];
__device__ float g_V[(size_t)NMAX * D];
__device__ float g_exp[(size_t)EMAX * H];
__device__ float g_norm[(size_t)NMAX * H];

typedef unsigned long long u64;

__device__ __forceinline__ void red_add_v4(float* addr, float4 v) {
    asm volatile("red.global.add.v4.f32 [%0], {%1, %2, %3, %4};"
                 :: "l"(addr), "f"(v.x), "f"(v.y), "f"(v.z), "f"(v.w)
                 : "memory");
}

__device__ __forceinline__ u64 pack2(float lo, float hi) {
    u64 r; asm("mov.b64 %0, {%1, %2};" : "=l"(r) : "f"(lo), "f"(hi)); return r;
}
__device__ __forceinline__ u64 fma2(u64 a, u64 b, u64 c) {
    u64 d; asm("fma.rn.f32x2 %0, %1, %2, %3;" : "=l"(d) : "l"(a), "l"(b), "l"(c)); return d;
}
__device__ __forceinline__ float2 unpack2(u64 v) {
    float2 r; asm("mov.b64 {%0, %1}, %2;" : "=f"(r.x), "=f"(r.y) : "l"(v)); return r;
}

// ---------------------------------------------------------------------------
// Zero d_out and g_norm (atomics accumulate into both; must re-zero per call)
// ---------------------------------------------------------------------------
__global__ void zero_kernel(float4* out, int n_out4, int n_norm4) {
    int i = blockIdx.x * blockDim.x + threadIdx.x;
    float4 z = make_float4(0.f, 0.f, 0.f, 0.f);
    if (i < n_out4) {
        out[i] = z;
    } else if (i < n_out4 + n_norm4) {
        ((float4*)g_norm)[i - n_out4] = z;
    }
}

// ---------------------------------------------------------------------------
// QKV projection: O = A @ W for W in {qW, kW, vW} (blockIdx.y selects).
// Block tile 128 rows x 128 cols, K = 128 (full). 256 threads, 8x8 microtile,
// packed f32x2 FMA (2 cols per accumulator pair).
// ---------------------------------------------------------------------------
__global__ void qkv_gemm(const float* __restrict__ A,
                         const float* __restrict__ Wq,
                         const float* __restrict__ Wk,
                         const float* __restrict__ Wv,
                         int N) {
    extern __shared__ float smem[];
    float* As = smem;           // [128][128] row-major [row][k]
    float* Bs = smem + D * D;   // [128][128] [k][n]

    const float* W = (blockIdx.y == 0) ? Wq : (blockIdx.y == 1) ? Wk : Wv;
    float* O       = (blockIdx.y == 0) ? g_Q : (blockIdx.y == 1) ? g_K : g_V;

    int tid  = threadIdx.x;
    int row0 = blockIdx.x * 128;

    // Cooperative load: 128x128 floats each for A tile and W (16 float4/thread)
#pragma unroll
    for (int i = 0; i < 16; i++) {
        int idx4 = tid + i * 256;       // float4 index, 0..4095
        int r  = idx4 >> 5;             // 32 float4 per row
        int kq = idx4 & 31;
        float4 av = make_float4(0.f, 0.f, 0.f, 0.f);
        if (row0 + r < N)
            av = *(const float4*)(A + (size_t)(row0 + r) * D + kq * 4);
        *(float4*)(As + r * D + kq * 4) = av;
        *(float4*)(Bs + r * D + kq * 4) = *(const float4*)(W + r * D + kq * 4);
    }
    __syncthreads();

    int tx = tid & 15, ty = tid >> 4;
    int rbase = ty * 8, cbase = tx * 8;

    u64 acc[8][4];
#pragma unroll
    for (int i = 0; i < 8; i++)
#pragma unroll
        for (int j = 0; j < 4; j++) acc[i][j] = 0ull;

#pragma unroll 2
    for (int kk = 0; kk < D; kk += 4) {
        float4 a4[8];
#pragma unroll
        for (int i = 0; i < 8; i++)
            a4[i] = *(float4*)(As + (rbase + i) * D + kk);
#pragma unroll
        for (int u = 0; u < 4; u++) {
            float4 b0 = *(float4*)(Bs + (kk + u) * D + cbase);
            float4 b1 = *(float4*)(Bs + (kk + u) * D + cbase + 4);
            u64 bp0 = pack2(b0.x, b0.y);
            u64 bp1 = pack2(b0.z, b0.w);
            u64 bp2 = pack2(b1.x, b1.y);
            u64 bp3 = pack2(b1.z, b1.w);
#pragma unroll
            for (int i = 0; i < 8; i++) {
                float a = (u == 0) ? a4[i].x : (u == 1) ? a4[i].y
                        : (u == 2) ? a4[i].z : a4[i].w;
                u64 a2 = pack2(a, a);
                acc[i][0] = fma2(a2, bp0, acc[i][0]);
                acc[i][1] = fma2(a2, bp1, acc[i][1]);
                acc[i][2] = fma2(a2, bp2, acc[i][2]);
                acc[i][3] = fma2(a2, bp3, acc[i][3]);
            }
        }
    }

#pragma unroll
    for (int i = 0; i < 8; i++) {
        int row = row0 + rbase + i;
        if (row < N) {
            float2 c0 = unpack2(acc[i][0]);
            float2 c1 = unpack2(acc[i][1]);
            float2 c2 = unpack2(acc[i][2]);
            float2 c3 = unpack2(acc[i][3]);
            *(float4*)(O + (size_t)row * D + cbase)     = make_float4(c0.x, c0.y, c1.x, c1.y);
            *(float4*)(O + (size_t)row * D + cbase + 4) = make_float4(c2.x, c2.y, c3.x, c3.y);
        }
    }
}

// ---------------------------------------------------------------------------
// Edge pass 1: per-edge per-head logits -> exp -> store + segment-sum denom.
// One warp per edge; lane l owns elements [4l, 4l+4); head h = l >> 3.
// ---------------------------------------------------------------------------
__global__ void edge_pass1(const int* __restrict__ rows,
                           const int* __restrict__ cols, int E) {
    int gw   = (blockIdx.x * blockDim.x + threadIdx.x) >> 5;
    int lane = threadIdx.x & 31;
    if (gw >= E) return;

    int r = __ldg(rows + gw);
    int c = __ldg(cols + gw);

    float4 q = *(const float4*)(g_Q + (size_t)r * D + lane * 4);
    float4 k = *(const float4*)(g_K + (size_t)c * D + lane * 4);
    float d = q.x * k.x + q.y * k.y + q.z * k.z + q.w * k.w;
    // Reduce within each 8-lane group (= one head, 32 elements)
    d += __shfl_xor_sync(0xffffffffu, d, 1);
    d += __shfl_xor_sync(0xffffffffu, d, 2);
    d += __shfl_xor_sync(0xffffffffu, d, 4);

    float att = fminf(10.0f, fmaxf(-10.0f, d));
    float ex  = expf(att);

    float a0 = __shfl_sync(0xffffffffu, ex, 0);
    float a1 = __shfl_sync(0xffffffffu, ex, 8);
    float a2 = __shfl_sync(0xffffffffu, ex, 16);
    float a3 = __shfl_sync(0xffffffffu, ex, 24);

    if (lane == 0) {
        float4 v4 = make_float4(a0, a1, a2, a3);
        *(float4*)(g_exp + (size_t)gw * H) = v4;
        red_add_v4(g_norm + (size_t)r * H, v4);
    }
}

// ---------------------------------------------------------------------------
// Edge pass 2: att = exp/(norm+1e-8); out[row] += att[h] * V[col]
// ---------------------------------------------------------------------------
__global__ void edge_pass2(const int* __restrict__ rows,
                           const int* __restrict__ cols, int E,
                           float* __restrict__ out) {
    int gw   = (blockIdx.x * blockDim.x + threadIdx.x) >> 5;
    int lane = threadIdx.x & 31;
    if (gw >= E) return;

    int r = __ldg(rows + gw);
    int c = __ldg(cols + gw);

    float4 ex = *(const float4*)(g_exp + (size_t)gw * H);
    float4 nm = *(const float4*)(g_norm + (size_t)r * H);

    int h   = lane >> 3;
    float e = (h == 0) ? ex.x : (h == 1) ? ex.y : (h == 2) ? ex.z : ex.w;
    float n = (h == 0) ? nm.x : (h == 1) ? nm.y : (h == 2) ? nm.z : nm.w;
    float a = e / (n + 1e-8f);

    float4 v = *(const float4*)(g_V + (size_t)c * D + lane * 4);
    red_add_v4(out + (size_t)r * D + lane * 4,
               make_float4(a * v.x, a * v.y, a * v.z, a * v.w));
}

// ---------------------------------------------------------------------------
extern "C" void kernel_launch(void* const* d_in, const int* in_sizes, int n_in,
                              void* d_out, int out_size) {
    const float* embeds = (const float*)d_in[0];
    const float* qW     = (const float*)d_in[1];
    const float* kW     = (const float*)d_in[2];
    const float* vW     = (const float*)d_in[3];
    const int*   rows   = (const int*)d_in[4];
    const int*   cols   = (const int*)d_in[5];

    int N = in_sizes[0] / D;
    int E = in_sizes[4];
    float* out = (float*)d_out;

    // 1) zero out + norm
    int n_out4  = N * D / 4;
    int n_norm4 = N * H / 4;
    int total4  = n_out4 + n_norm4;
    zero_kernel<<<(total4 + 255) / 256, 256>>>((float4*)out, n_out4, n_norm4);

    // 2) QKV projection
    size_t smem_bytes = 2 * (size_t)D * D * sizeof(float);  // 128 KB
    cudaFuncSetAttribute(qkv_gemm, cudaFuncAttributeMaxDynamicSharedMemorySize,
                         (int)smem_bytes);
    dim3 ggrid((N + 127) / 128, 3);
    qkv_gemm<<<ggrid, 256, smem_bytes>>>(embeds, qW, kW, vW, N);

    // 3) edge logits + softmax denominators (one warp per edge)
    int blocks = (E + 7) / 8;  // 8 warps per 256-thread block
    edge_pass1<<<blocks, 256>>>(rows, cols, E);

    // 4) softmax-normalize + weighted aggregate
    edge_pass2<<<blocks, 256>>>(rows, cols, E, out);
}

// round 2
// speedup vs baseline: 1.4719x; 1.4719x over previous
#include <cuda_runtime.h>

#define D 128
#define H 4
#define NMAX 50000
#define EMAX 600000

// Scratch (device globals: allocation inside kernel_launch is forbidden)
__device__ float g_Q[(size_t)NMAX * D];
__device__ float g_K[(size_t)NMAX * D];
__device__ float g_V[(size_t)NMAX * D];
__device__ float g_norm[(size_t)NMAX * H];

typedef unsigned long long u64;

__device__ __forceinline__ void red_add_v4(float* addr, float4 v) {
    asm volatile("red.global.add.v4.f32 [%0], {%1, %2, %3, %4};"
                 :: "l"(addr), "f"(v.x), "f"(v.y), "f"(v.z), "f"(v.w)
                 : "memory");
}
__device__ __forceinline__ void red_add_f32(float* addr, float v) {
    asm volatile("red.global.add.f32 [%0], %1;"
                 :: "l"(addr), "f"(v) : "memory");
}

__device__ __forceinline__ u64 pack2(float lo, float hi) {
    u64 r; asm("mov.b64 %0, {%1, %2};" : "=l"(r) : "f"(lo), "f"(hi)); return r;
}
__device__ __forceinline__ u64 fma2(u64 a, u64 b, u64 c) {
    u64 d; asm("fma.rn.f32x2 %0, %1, %2, %3;" : "=l"(d) : "l"(a), "l"(b), "l"(c)); return d;
}
__device__ __forceinline__ float2 unpack2(u64 v) {
    float2 r; asm("mov.b64 {%0, %1}, %2;" : "=f"(r.x), "=f"(r.y) : "l"(v)); return r;
}

// ---------------------------------------------------------------------------
// Zero d_out and g_norm (atomics accumulate into both; must re-zero per call)
// ---------------------------------------------------------------------------
__global__ void zero_kernel(float4* out, int n_out4, int n_norm4) {
    int i = blockIdx.x * blockDim.x + threadIdx.x;
    float4 z = make_float4(0.f, 0.f, 0.f, 0.f);
    if (i < n_out4) {
        out[i] = z;
    } else if (i < n_out4 + n_norm4) {
        ((float4*)g_norm)[i - n_out4] = z;
    }
}

// ---------------------------------------------------------------------------
// QKV projection: O = A @ W for W in {qW, kW, vW} (blockIdx.y selects).
// Block tile 128 rows x 128 cols, K = 128 (full). 256 threads, 8x8 microtile,
// packed f32x2 FMA (2 cols per accumulator pair).
// ---------------------------------------------------------------------------
__global__ void qkv_gemm(const float* __restrict__ A,
                         const float* __restrict__ Wq,
                         const float* __restrict__ Wk,
                         const float* __restrict__ Wv,
                         int N) {
    extern __shared__ float smem[];
    float* As = smem;           // [128][128] row-major [row][k]
    float* Bs = smem + D * D;   // [128][128] [k][n]

    const float* W = (blockIdx.y == 0) ? Wq : (blockIdx.y == 1) ? Wk : Wv;
    float* O       = (blockIdx.y == 0) ? g_Q : (blockIdx.y == 1) ? g_K : g_V;

    int tid  = threadIdx.x;
    int row0 = blockIdx.x * 128;

#pragma unroll
    for (int i = 0; i < 16; i++) {
        int idx4 = tid + i * 256;       // float4 index, 0..4095
        int r  = idx4 >> 5;             // 32 float4 per row
        int kq = idx4 & 31;
        float4 av = make_float4(0.f, 0.f, 0.f, 0.f);
        if (row0 + r < N)
            av = *(const float4*)(A + (size_t)(row0 + r) * D + kq * 4);
        *(float4*)(As + r * D + kq * 4) = av;
        *(float4*)(Bs + r * D + kq * 4) = *(const float4*)(W + r * D + kq * 4);
    }
    __syncthreads();

    int tx = tid & 15, ty = tid >> 4;
    int rbase = ty * 8, cbase = tx * 8;

    u64 acc[8][4];
#pragma unroll
    for (int i = 0; i < 8; i++)
#pragma unroll
        for (int j = 0; j < 4; j++) acc[i][j] = 0ull;

#pragma unroll 2
    for (int kk = 0; kk < D; kk += 4) {
        float4 a4[8];
#pragma unroll
        for (int i = 0; i < 8; i++)
            a4[i] = *(float4*)(As + (rbase + i) * D + kk);
#pragma unroll
        for (int u = 0; u < 4; u++) {
            float4 b0 = *(float4*)(Bs + (kk + u) * D + cbase);
            float4 b1 = *(float4*)(Bs + (kk + u) * D + cbase + 4);
            u64 bp0 = pack2(b0.x, b0.y);
            u64 bp1 = pack2(b0.z, b0.w);
            u64 bp2 = pack2(b1.x, b1.y);
            u64 bp3 = pack2(b1.z, b1.w);
#pragma unroll
            for (int i = 0; i < 8; i++) {
                float a = (u == 0) ? a4[i].x : (u == 1) ? a4[i].y
                        : (u == 2) ? a4[i].z : a4[i].w;
                u64 a2 = pack2(a, a);
                acc[i][0] = fma2(a2, bp0, acc[i][0]);
                acc[i][1] = fma2(a2, bp1, acc[i][1]);
                acc[i][2] = fma2(a2, bp2, acc[i][2]);
                acc[i][3] = fma2(a2, bp3, acc[i][3]);
            }
        }
    }

#pragma unroll
    for (int i = 0; i < 8; i++) {
        int row = row0 + rbase + i;
        if (row < N) {
            float2 c0 = unpack2(acc[i][0]);
            float2 c1 = unpack2(acc[i][1]);
            float2 c2 = unpack2(acc[i][2]);
            float2 c3 = unpack2(acc[i][3]);
            *(float4*)(O + (size_t)row * D + cbase)     = make_float4(c0.x, c0.y, c1.x, c1.y);
            *(float4*)(O + (size_t)row * D + cbase + 4) = make_float4(c2.x, c2.y, c3.x, c3.y);
        }
    }
}

// ---------------------------------------------------------------------------
// Fused edge pass: per-edge per-head logit -> exp -> red norm[row] AND
// red (exp * V[col]) into out[row] (UNNORMALIZED). Normalization happens in
// a per-node pass afterwards (denominator is constant per (row, head)).
// One warp per 2 edges; lane l owns elements [4l, 4l+4); head h = l >> 3.
// After the 8-lane xor-reduction every lane holds its own head's logit.
// ---------------------------------------------------------------------------
__global__ void edge_fused(const int* __restrict__ rows,
                           const int* __restrict__ cols, int E,
                           float* __restrict__ out) {
    int warp = (blockIdx.x * blockDim.x + threadIdx.x) >> 5;
    int lane = threadIdx.x & 31;
    int e0 = warp * 2;
    if (e0 >= E) return;
    bool has1 = (e0 + 1 < E);

    int r0 = __ldg(rows + e0);
    int c0 = __ldg(cols + e0);
    int r1 = has1 ? __ldg(rows + e0 + 1) : r0;
    int c1 = has1 ? __ldg(cols + e0 + 1) : c0;

    const float4* Q4 = (const float4*)g_Q;
    const float4* K4 = (const float4*)g_K;
    const float4* V4 = (const float4*)g_V;

    // 6 independent 128-B gathers in flight per warp
    float4 q0 = Q4[(size_t)r0 * 32 + lane];
    float4 k0 = K4[(size_t)c0 * 32 + lane];
    float4 v0 = V4[(size_t)c0 * 32 + lane];
    float4 q1 = Q4[(size_t)r1 * 32 + lane];
    float4 k1 = K4[(size_t)c1 * 32 + lane];
    float4 v1 = V4[(size_t)c1 * 32 + lane];

    float d0 = q0.x * k0.x + q0.y * k0.y + q0.z * k0.z + q0.w * k0.w;
    float d1 = q1.x * k1.x + q1.y * k1.y + q1.z * k1.z + q1.w * k1.w;
    d0 += __shfl_xor_sync(0xffffffffu, d0, 1);
    d1 += __shfl_xor_sync(0xffffffffu, d1, 1);
    d0 += __shfl_xor_sync(0xffffffffu, d0, 2);
    d1 += __shfl_xor_sync(0xffffffffu, d1, 2);
    d0 += __shfl_xor_sync(0xffffffffu, d0, 4);
    d1 += __shfl_xor_sync(0xffffffffu, d1, 4);

    float a0 = __expf(fminf(10.0f, fmaxf(-10.0f, d0)));
    float a1 = __expf(fminf(10.0f, fmaxf(-10.0f, d1)));

    int h = lane >> 3;
    // norm accumulation: one lane per head per edge
    if ((lane & 7) == 0) {
        red_add_f32(g_norm + (size_t)r0 * H + h, a0);
        if (has1) red_add_f32(g_norm + (size_t)r1 * H + h, a1);
    }

    red_add_v4(out + (size_t)r0 * D + lane * 4,
               make_float4(a0 * v0.x, a0 * v0.y, a0 * v0.z, a0 * v0.w));
    if (has1)
        red_add_v4(out + (size_t)r1 * D + lane * 4,
                   make_float4(a1 * v1.x, a1 * v1.y, a1 * v1.z, a1 * v1.w));
}

// ---------------------------------------------------------------------------
// Per-node normalize: out[n][h*32 .. h*32+31] /= (norm[n][h] + 1e-8)
// One thread per float4.
// ---------------------------------------------------------------------------
__global__ void normalize_kernel(float4* __restrict__ out, int N) {
    int i = blockIdx.x * blockDim.x + threadIdx.x;   // float4 index
    if (i >= N * 32) return;
    int node = i >> 5;
    int q4   = i & 31;
    int h    = q4 >> 3;
    float n   = __ldg(g_norm + (size_t)node * H + h);
    float inv = __frcp_rn(n + 1e-8f);
    float4 o = out[i];
    o.x *= inv; o.y *= inv; o.z *= inv; o.w *= inv;
    out[i] = o;
}

// ---------------------------------------------------------------------------
extern "C" void kernel_launch(void* const* d_in, const int* in_sizes, int n_in,
                              void* d_out, int out_size) {
    const float* embeds = (const float*)d_in[0];
    const float* qW     = (const float*)d_in[1];
    const float* kW     = (const float*)d_in[2];
    const float* vW     = (const float*)d_in[3];
    const int*   rows   = (const int*)d_in[4];
    const int*   cols   = (const int*)d_in[5];

    int N = in_sizes[0] / D;
    int E = in_sizes[4];
    float* out = (float*)d_out;

    // 1) zero out + norm
    int n_out4  = N * D / 4;
    int n_norm4 = N * H / 4;
    int total4  = n_out4 + n_norm4;
    zero_kernel<<<(total4 + 255) / 256, 256>>>((float4*)out, n_out4, n_norm4);

    // 2) QKV projection
    size_t smem_bytes = 2 * (size_t)D * D * sizeof(float);  // 128 KB
    cudaFuncSetAttribute(qkv_gemm, cudaFuncAttributeMaxDynamicSharedMemorySize,
                         (int)smem_bytes);
    dim3 ggrid((N + 127) / 128, 3);
    qkv_gemm<<<ggrid, 256, smem_bytes>>>(embeds, qW, kW, vW, N);

    // 3) fused edge pass (2 edges per warp)
    int warps  = (E + 1) / 2;
    int blocks = (warps + 7) / 8;   // 8 warps per 256-thread block
    edge_fused<<<blocks, 256>>>(rows, cols, E, out);

    // 4) per-node softmax normalization
    int nthreads = N * 32;
    normalize_kernel<<<(nthreads + 255) / 256, 256>>>((float4*)out, N);
}

// round 3
// speedup vs baseline: 1.5303x; 1.0397x over previous
#include <cuda_runtime.h>

#define D 128
#define H 4
#define NMAX 50000
#define EMAX 600000
#define SCAN_ELEMS 1024   // elements per scan block (256 threads x 4)
#define MAX_SCAN_BLOCKS 64

// Scratch (device globals: allocation inside kernel_launch is forbidden)
__device__ float g_Q[(size_t)NMAX * D];
__device__ float g_K[(size_t)NMAX * D];
__device__ float g_V[(size_t)NMAX * D];
__device__ int   g_cnt[NMAX];
__device__ int   g_rs[NMAX + 1];       // row_start (CSR)
__device__ int   g_cur[NMAX];          // scatter cursors
__device__ int   g_bsum[MAX_SCAN_BLOCKS];
__device__ int   g_bofs[MAX_SCAN_BLOCKS];
__device__ int   g_scol[EMAX];         // cols sorted by row

typedef unsigned long long u64;

__device__ __forceinline__ u64 pack2(float lo, float hi) {
    u64 r; asm("mov.b64 %0, {%1, %2};" : "=l"(r) : "f"(lo), "f"(hi)); return r;
}
__device__ __forceinline__ u64 fma2(u64 a, u64 b, u64 c) {
    u64 d; asm("fma.rn.f32x2 %0, %1, %2, %3;" : "=l"(d) : "l"(a), "l"(b), "l"(c)); return d;
}
__device__ __forceinline__ float2 unpack2(u64 v) {
    float2 r; asm("mov.b64 {%0, %1}, %2;" : "=f"(r.x), "=f"(r.y) : "l"(v)); return r;
}

// ---------------------------------------------------------------------------
// Zero the row-degree counters
// ---------------------------------------------------------------------------
__global__ void zero_cnt(int N) {
    int i = blockIdx.x * blockDim.x + threadIdx.x;
    if (i * 4 < N) ((int4*)g_cnt)[i] = make_int4(0, 0, 0, 0);
}

// ---------------------------------------------------------------------------
// Histogram of row ids
// ---------------------------------------------------------------------------
__global__ void hist_kernel(const int* __restrict__ rows, int E) {
    int i = blockIdx.x * blockDim.x + threadIdx.x;
    if (i < E) atomicAdd(g_cnt + __ldg(rows + i), 1);
}

// ---------------------------------------------------------------------------
// Scan step 1: per-block exclusive scan of g_cnt -> g_rs, block totals g_bsum
// ---------------------------------------------------------------------------
__global__ void scan1(int N) {
    __shared__ int sh[256];
    int b = blockIdx.x, t = threadIdx.x;
    int base = b * SCAN_ELEMS + t * 4;

    int4 v = make_int4(0, 0, 0, 0);
    if (base + 3 < N) {
        v = *(const int4*)(g_cnt + base);
    } else {
        if (base + 0 < N) v.x = g_cnt[base + 0];
        if (base + 1 < N) v.y = g_cnt[base + 1];
        if (base + 2 < N) v.z = g_cnt[base + 2];
        if (base + 3 < N) v.w = g_cnt[base + 3];
    }
    int s = v.x + v.y + v.z + v.w;
    sh[t] = s;
    __syncthreads();
    // Hillis-Steele inclusive scan over 256 thread sums
    for (int off = 1; off < 256; off <<= 1) {
        int val = (t >= off) ? sh[t - off] : 0;
        __syncthreads();
        sh[t] += val;
        __syncthreads();
    }
    int excl = sh[t] - s;
    if (t == 255) g_bsum[b] = sh[255];

    int p = excl;
    if (base + 0 < N) g_rs[base + 0] = p; p += v.x;
    if (base + 1 < N) g_rs[base + 1] = p; p += v.y;
    if (base + 2 < N) g_rs[base + 2] = p; p += v.z;
    if (base + 3 < N) g_rs[base + 3] = p;
}

// ---------------------------------------------------------------------------
// Scan step 2: exclusive scan of block totals (single thread; nb <= 64)
// ---------------------------------------------------------------------------
__global__ void scan2(int nb) {
    if (threadIdx.x == 0) {
        int acc = 0;
        for (int i = 0; i < nb; i++) {
            g_bofs[i] = acc;
            acc += g_bsum[i];
        }
    }
}

// ---------------------------------------------------------------------------
// Scan step 3: add block offsets; init cursors; set sentinel
// ---------------------------------------------------------------------------
__global__ void scan3(int N, int E) {
    int i = blockIdx.x * blockDim.x + threadIdx.x;
    if (i < N) {
        int v = g_rs[i] + g_bofs[i / SCAN_ELEMS];
        g_rs[i]  = v;
        g_cur[i] = v;
    }
    if (i == 0) g_rs[N] = E;
}

// ---------------------------------------------------------------------------
// Scatter cols into row-sorted order
// ---------------------------------------------------------------------------
__global__ void scatter_kernel(const int* __restrict__ rows,
                               const int* __restrict__ cols, int E) {
    int i = blockIdx.x * blockDim.x + threadIdx.x;
    if (i < E) {
        int r = __ldg(rows + i);
        int pos = atomicAdd(g_cur + r, 1);
        g_scol[pos] = __ldg(cols + i);
    }
}

// ---------------------------------------------------------------------------
// QKV projection: O = A @ W for W in {qW, kW, vW} (blockIdx.y selects).
// Block tile 128 rows x 128 cols, K = 128 (full). 256 threads, 8x8 microtile,
// packed f32x2 FMA (2 cols per accumulator pair).
// ---------------------------------------------------------------------------
__global__ void qkv_gemm(const float* __restrict__ A,
                         const float* __restrict__ Wq,
                         const float* __restrict__ Wk,
                         const float* __restrict__ Wv,
                         int N) {
    extern __shared__ float smem[];
    float* As = smem;           // [128][128] row-major [row][k]
    float* Bs = smem + D * D;   // [128][128] [k][n]

    const float* W = (blockIdx.y == 0) ? Wq : (blockIdx.y == 1) ? Wk : Wv;
    float* O       = (blockIdx.y == 0) ? g_Q : (blockIdx.y == 1) ? g_K : g_V;

    int tid  = threadIdx.x;
    int row0 = blockIdx.x * 128;

#pragma unroll
    for (int i = 0; i < 16; i++) {
        int idx4 = tid + i * 256;       // float4 index, 0..4095
        int r  = idx4 >> 5;             // 32 float4 per row
        int kq = idx4 & 31;
        float4 av = make_float4(0.f, 0.f, 0.f, 0.f);
        if (row0 + r < N)
            av = *(const float4*)(A + (size_t)(row0 + r) * D + kq * 4);
        *(float4*)(As + r * D + kq * 4) = av;
        *(float4*)(Bs + r * D + kq * 4) = *(const float4*)(W + r * D + kq * 4);
    }
    __syncthreads();

    int tx = tid & 15, ty = tid >> 4;
    int rbase = ty * 8, cbase = tx * 8;

    u64 acc[8][4];
#pragma unroll
    for (int i = 0; i < 8; i++)
#pragma unroll
        for (int j = 0; j < 4; j++) acc[i][j] = 0ull;

#pragma unroll 2
    for (int kk = 0; kk < D; kk += 4) {
        float4 a4[8];
#pragma unroll
        for (int i = 0; i < 8; i++)
            a4[i] = *(float4*)(As + (rbase + i) * D + kk);
#pragma unroll
        for (int u = 0; u < 4; u++) {
            float4 b0 = *(float4*)(Bs + (kk + u) * D + cbase);
            float4 b1 = *(float4*)(Bs + (kk + u) * D + cbase + 4);
            u64 bp0 = pack2(b0.x, b0.y);
            u64 bp1 = pack2(b0.z, b0.w);
            u64 bp2 = pack2(b1.x, b1.y);
            u64 bp3 = pack2(b1.z, b1.w);
#pragma unroll
            for (int i = 0; i < 8; i++) {
                float a = (u == 0) ? a4[i].x : (u == 1) ? a4[i].y
                        : (u == 2) ? a4[i].z : a4[i].w;
                u64 a2 = pack2(a, a);
                acc[i][0] = fma2(a2, bp0, acc[i][0]);
                acc[i][1] = fma2(a2, bp1, acc[i][1]);
                acc[i][2] = fma2(a2, bp2, acc[i][2]);
                acc[i][3] = fma2(a2, bp3, acc[i][3]);
            }
        }
    }

#pragma unroll
    for (int i = 0; i < 8; i++) {
        int row = row0 + rbase + i;
        if (row < N) {
            float2 c0 = unpack2(acc[i][0]);
            float2 c1 = unpack2(acc[i][1]);
            float2 c2 = unpack2(acc[i][2]);
            float2 c3 = unpack2(acc[i][3]);
            *(float4*)(O + (size_t)row * D + cbase)     = make_float4(c0.x, c0.y, c1.x, c1.y);
            *(float4*)(O + (size_t)row * D + cbase + 4) = make_float4(c2.x, c2.y, c3.x, c3.y);
        }
    }
}

// ---------------------------------------------------------------------------
// Row processing: one warp per node row. Loads Q[row] once, iterates the
// row's edges (CSR), gathers K/V per edge, accumulates exp-weighted sum and
// softmax denominator in registers, writes the normalized row with STG.
// Lane l owns float4 chunk l; head h = lane >> 3. After the 8-lane xor
// reduction each lane holds its own head's logit.
// ---------------------------------------------------------------------------
__global__ void row_process(float4* __restrict__ out, int N) {
    int row  = (blockIdx.x * blockDim.x + threadIdx.x) >> 5;
    int lane = threadIdx.x & 31;
    if (row >= N) return;

    int s = g_rs[row];
    int e = g_rs[row + 1];

    const float4* Q4 = (const float4*)g_Q;
    const float4* K4 = (const float4*)g_K;
    const float4* V4 = (const float4*)g_V;

    float4 q = Q4[(size_t)row * 32 + lane];
    float4 acc = make_float4(0.f, 0.f, 0.f, 0.f);
    float nrm = 0.f;

    float4 k4, v4;
    if (s < e) {
        int c = __ldg(g_scol + s);
        k4 = K4[(size_t)c * 32 + lane];
        v4 = V4[(size_t)c * 32 + lane];
    }
    for (int j = s; j < e; j++) {
        float4 kc = k4, vc = v4;
        if (j + 1 < e) {
            int c = __ldg(g_scol + j + 1);
            k4 = K4[(size_t)c * 32 + lane];
            v4 = V4[(size_t)c * 32 + lane];
        }
        float d = q.x * kc.x + q.y * kc.y + q.z * kc.z + q.w * kc.w;
        d += __shfl_xor_sync(0xffffffffu, d, 1);
        d += __shfl_xor_sync(0xffffffffu, d, 2);
        d += __shfl_xor_sync(0xffffffffu, d, 4);
        float ex = __expf(fminf(10.0f, fmaxf(-10.0f, d)));
        nrm += ex;
        acc.x += ex * vc.x;
        acc.y += ex * vc.y;
        acc.z += ex * vc.z;
        acc.w += ex * vc.w;
    }

    float inv = 1.0f / (nrm + 1e-8f);
    out[(size_t)row * 32 + lane] =
        make_float4(acc.x * inv, acc.y * inv, acc.z * inv, acc.w * inv);
}

// ---------------------------------------------------------------------------
extern "C" void kernel_launch(void* const* d_in, const int* in_sizes, int n_in,
                              void* d_out, int out_size) {
    const float* embeds = (const float*)d_in[0];
    const float* qW     = (const float*)d_in[1];
    const float* kW     = (const float*)d_in[2];
    const float* vW     = (const float*)d_in[3];
    const int*   rows   = (const int*)d_in[4];
    const int*   cols   = (const int*)d_in[5];

    int N = in_sizes[0] / D;
    int E = in_sizes[4];
    float* out = (float*)d_out;

    // --- CSR build ---
    zero_cnt<<<(N / 4 + 255) / 256, 256>>>(N);
    hist_kernel<<<(E + 255) / 256, 256>>>(rows, E);
    int nb = (N + SCAN_ELEMS - 1) / SCAN_ELEMS;
    scan1<<<nb, 256>>>(N);
    scan2<<<1, 32>>>(nb);
    scan3<<<(N + 255) / 256, 256>>>(N, E);
    scatter_kernel<<<(E + 255) / 256, 256>>>(rows, cols, E);

    // --- QKV projection ---
    size_t smem_bytes = 2 * (size_t)D * D * sizeof(float);  // 128 KB
    cudaFuncSetAttribute(qkv_gemm, cudaFuncAttributeMaxDynamicSharedMemorySize,
                         (int)smem_bytes);
    dim3 ggrid((N + 127) / 128, 3);
    qkv_gemm<<<ggrid, 256, smem_bytes>>>(embeds, qW, kW, vW, N);

    // --- Per-row attention + aggregation (register accumulation, no atomics)
    int warps  = N;
    int blocks = (warps + 7) / 8;   // 8 warps per 256-thread block
    row_process<<<blocks, 256>>>((float4*)out, N);
}

// round 4
// speedup vs baseline: 1.5801x; 1.0325x over previous
#include <cuda_runtime.h>

#define D 128
#define H 4
#define NMAX 50000
#define EMAX 600000
#define SCAN_ELEMS 1024   // elements per scan block (256 threads x 4)
#define MAX_SCAN_BLOCKS 64
#define HIST_BLOCKS 148

// Scratch (device globals: allocation inside kernel_launch is forbidden)
__device__ float g_Q [(size_t)NMAX * D];
__device__ float g_KV[(size_t)NMAX * 2 * D];   // per node: K[128] | V[128]
__device__ int   g_cnt[NMAX];
__device__ int   g_rs[NMAX + 1];               // row_start (CSR)
__device__ int   g_cur[NMAX];                  // scatter cursors
__device__ int   g_bsum[MAX_SCAN_BLOCKS];
__device__ int   g_scol[EMAX];                 // cols sorted by row

typedef unsigned long long u64;

__device__ __forceinline__ u64 pack2(float lo, float hi) {
    u64 r; asm("mov.b64 %0, {%1, %2};" : "=l"(r) : "f"(lo), "f"(hi)); return r;
}
__device__ __forceinline__ u64 fma2(u64 a, u64 b, u64 c) {
    u64 d; asm("fma.rn.f32x2 %0, %1, %2, %3;" : "=l"(d) : "l"(a), "l"(b), "l"(c)); return d;
}
__device__ __forceinline__ float2 unpack2(u64 v) {
    float2 r; asm("mov.b64 {%0, %1}, %2;" : "=f"(r.x), "=f"(r.y) : "l"(v)); return r;
}

// ---------------------------------------------------------------------------
// Fused QKV projection + row histogram (grid-partition fusion).
// Blocks [0, 3*GB): GEMM  O = A @ W, 128x128 tile, K=128 full depth.
//   which = b / GB selects {qW->g_Q, kW->g_KV[:,0:128], vW->g_KV[:,128:256]}.
// Blocks [3*GB, 3*GB + HIST_BLOCKS): grid-stride histogram of row ids.
// ---------------------------------------------------------------------------
__global__ void gemm_hist(const float* __restrict__ A,
                          const float* __restrict__ Wq,
                          const float* __restrict__ Wk,
                          const float* __restrict__ Wv,
                          const int* __restrict__ rows,
                          int N, int E, int GB) {
    extern __shared__ float smem[];
    int b = blockIdx.x;

    if (b >= 3 * GB) {
        // ---- histogram part ----
        int i = (b - 3 * GB) * blockDim.x + threadIdx.x;
        int stride = HIST_BLOCKS * blockDim.x;
        for (; i < E; i += stride)
            atomicAdd(g_cnt + __ldg(rows + i), 1);
        return;
    }

    // ---- GEMM part ----
    float* As = smem;           // [128][128] row-major [row][k]
    float* Bs = smem + D * D;   // [128][128] [k][n]

    int which = b / GB;
    int tileb = b - which * GB;

    const float* W = (which == 0) ? Wq : (which == 1) ? Wk : Wv;
    float* O;
    int ostride, ooff;
    if (which == 0)      { O = g_Q;  ostride = D;     ooff = 0; }
    else if (which == 1) { O = g_KV; ostride = 2 * D; ooff = 0; }
    else                 { O = g_KV; ostride = 2 * D; ooff = D; }

    int tid  = threadIdx.x;
    int row0 = tileb * 128;

#pragma unroll
    for (int i = 0; i < 16; i++) {
        int idx4 = tid + i * 256;       // float4 index, 0..4095
        int r  = idx4 >> 5;             // 32 float4 per row
        int kq = idx4 & 31;
        float4 av = make_float4(0.f, 0.f, 0.f, 0.f);
        if (row0 + r < N)
            av = *(const float4*)(A + (size_t)(row0 + r) * D + kq * 4);
        *(float4*)(As + r * D + kq * 4) = av;
        *(float4*)(Bs + r * D + kq * 4) = *(const float4*)(W + r * D + kq * 4);
    }
    __syncthreads();

    int tx = tid & 15, ty = tid >> 4;
    int rbase = ty * 8, cbase = tx * 8;

    u64 acc[8][4];
#pragma unroll
    for (int i = 0; i < 8; i++)
#pragma unroll
        for (int j = 0; j < 4; j++) acc[i][j] = 0ull;

#pragma unroll 2
    for (int kk = 0; kk < D; kk += 4) {
        float4 a4[8];
#pragma unroll
        for (int i = 0; i < 8; i++)
            a4[i] = *(float4*)(As + (rbase + i) * D + kk);
#pragma unroll
        for (int u = 0; u < 4; u++) {
            float4 b0 = *(float4*)(Bs + (kk + u) * D + cbase);
            float4 b1 = *(float4*)(Bs + (kk + u) * D + cbase + 4);
            u64 bp0 = pack2(b0.x, b0.y);
            u64 bp1 = pack2(b0.z, b0.w);
            u64 bp2 = pack2(b1.x, b1.y);
            u64 bp3 = pack2(b1.z, b1.w);
#pragma unroll
            for (int i = 0; i < 8; i++) {
                float a = (u == 0) ? a4[i].x : (u == 1) ? a4[i].y
                        : (u == 2) ? a4[i].z : a4[i].w;
                u64 a2 = pack2(a, a);
                acc[i][0] = fma2(a2, bp0, acc[i][0]);
                acc[i][1] = fma2(a2, bp1, acc[i][1]);
                acc[i][2] = fma2(a2, bp2, acc[i][2]);
                acc[i][3] = fma2(a2, bp3, acc[i][3]);
            }
        }
    }

#pragma unroll
    for (int i = 0; i < 8; i++) {
        int row = row0 + rbase + i;
        if (row < N) {
            float2 c0 = unpack2(acc[i][0]);
            float2 c1 = unpack2(acc[i][1]);
            float2 c2 = unpack2(acc[i][2]);
            float2 c3 = unpack2(acc[i][3]);
            float* op = O + (size_t)row * ostride + ooff + cbase;
            *(float4*)(op)     = make_float4(c0.x, c0.y, c1.x, c1.y);
            *(float4*)(op + 4) = make_float4(c2.x, c2.y, c3.x, c3.y);
        }
    }
}

// ---------------------------------------------------------------------------
// Scan step 1: per-block exclusive scan of g_cnt -> g_rs, block totals g_bsum
// ---------------------------------------------------------------------------
__global__ void scan1(int N) {
    __shared__ int sh[256];
    int b = blockIdx.x, t = threadIdx.x;
    int base = b * SCAN_ELEMS + t * 4;

    int4 v = make_int4(0, 0, 0, 0);
    if (base + 3 < N) {
        v = *(const int4*)(g_cnt + base);
    } else {
        if (base + 0 < N) v.x = g_cnt[base + 0];
        if (base + 1 < N) v.y = g_cnt[base + 1];
        if (base + 2 < N) v.z = g_cnt[base + 2];
        if (base + 3 < N) v.w = g_cnt[base + 3];
    }
    int s = v.x + v.y + v.z + v.w;
    sh[t] = s;
    __syncthreads();
    // Hillis-Steele inclusive scan over 256 thread sums
    for (int off = 1; off < 256; off <<= 1) {
        int val = (t >= off) ? sh[t - off] : 0;
        __syncthreads();
        sh[t] += val;
        __syncthreads();
    }
    int excl = sh[t] - s;
    if (t == 255) g_bsum[b] = sh[255];

    int p = excl;
    if (base + 0 < N) g_rs[base + 0] = p; p += v.x;
    if (base + 1 < N) g_rs[base + 1] = p; p += v.y;
    if (base + 2 < N) g_rs[base + 2] = p; p += v.z;
    if (base + 3 < N) g_rs[base + 3] = p;
}

// ---------------------------------------------------------------------------
// Scan steps 2+3 fused: each block redundantly computes its own block-offset
// prefix (<= 49 L2-cached loads), then applies it and initializes cursors.
// ---------------------------------------------------------------------------
__global__ void scan23(int N, int E) {
    __shared__ int s_off;
    int b = blockIdx.x, t = threadIdx.x;
    if (t == 0) {
        int acc = 0;
        for (int i = 0; i < b; i++) acc += g_bsum[i];
        s_off = acc;
    }
    __syncthreads();
    int off = s_off;
    int base = b * SCAN_ELEMS + t * 4;
#pragma unroll
    for (int u = 0; u < 4; u++) {
        int i = base + u;
        if (i < N) {
            int v = g_rs[i] + off;
            g_rs[i]  = v;
            g_cur[i] = v;
        }
    }
    if (b == 0 && t == 0) g_rs[N] = E;
}

// ---------------------------------------------------------------------------
// Scatter cols into row-sorted order
// ---------------------------------------------------------------------------
__global__ void scatter_kernel(const int* __restrict__ rows,
                               const int* __restrict__ cols, int E) {
    int i = blockIdx.x * blockDim.x + threadIdx.x;
    if (i < E) {
        int r = __ldg(rows + i);
        int pos = atomicAdd(g_cur + r, 1);
        g_scol[pos] = __ldg(cols + i);
    }
}

// ---------------------------------------------------------------------------
// Row processing: one warp per node row. Loads Q[row] once, iterates the
// row's edges (CSR), gathers interleaved K|V per edge (one contiguous 1 KB
// region per node), accumulates exp-weighted sum + softmax denominator in
// registers, writes the normalized row with STG. No atomics.
// ---------------------------------------------------------------------------
__global__ void row_process(float4* __restrict__ out, int N) {
    int row  = (blockIdx.x * blockDim.x + threadIdx.x) >> 5;
    int lane = threadIdx.x & 31;
    if (row >= N) return;

    int s = __ldg(g_rs + row);
    int e = __ldg(g_rs + row + 1);

    const float4* Q4  = (const float4*)g_Q;
    const float4* KV4 = (const float4*)g_KV;

    float4 q = Q4[(size_t)row * 32 + lane];
    float4 acc = make_float4(0.f, 0.f, 0.f, 0.f);
    float nrm = 0.f;

    float4 k4, v4;
    if (s < e) {
        int c = __ldg(g_scol + s);
        k4 = KV4[(size_t)c * 64 + lane];
        v4 = KV4[(size_t)c * 64 + 32 + lane];
    }
    for (int j = s; j < e; j++) {
        float4 kc = k4, vc = v4;
        if (j + 1 < e) {
            int c = __ldg(g_scol + j + 1);
            k4 = KV4[(size_t)c * 64 + lane];
            v4 = KV4[(size_t)c * 64 + 32 + lane];
        }
        float d = q.x * kc.x + q.y * kc.y + q.z * kc.z + q.w * kc.w;
        d += __shfl_xor_sync(0xffffffffu, d, 1);
        d += __shfl_xor_sync(0xffffffffu, d, 2);
        d += __shfl_xor_sync(0xffffffffu, d, 4);
        float ex = __expf(fminf(10.0f, fmaxf(-10.0f, d)));
        nrm += ex;
        acc.x += ex * vc.x;
        acc.y += ex * vc.y;
        acc.z += ex * vc.z;
        acc.w += ex * vc.w;
    }

    float inv = 1.0f / (nrm + 1e-8f);
    out[(size_t)row * 32 + lane] =
        make_float4(acc.x * inv, acc.y * inv, acc.z * inv, acc.w * inv);
}

// ---------------------------------------------------------------------------
extern "C" void kernel_launch(void* const* d_in, const int* in_sizes, int n_in,
                              void* d_out, int out_size) {
    const float* embeds = (const float*)d_in[0];
    const float* qW     = (const float*)d_in[1];
    const float* kW     = (const float*)d_in[2];
    const float* vW     = (const float*)d_in[3];
    const int*   rows   = (const int*)d_in[4];
    const int*   cols   = (const int*)d_in[5];

    int N = in_sizes[0] / D;
    int E = in_sizes[4];
    float* out = (float*)d_out;

    // 1) zero row-degree counters (memset node)
    void* cnt_ptr = nullptr;
    cudaGetSymbolAddress(&cnt_ptr, g_cnt);
    cudaMemsetAsync(cnt_ptr, 0, (size_t)N * sizeof(int));

    // 2) fused QKV projection + histogram
    int GB = (N + 127) / 128;
    size_t smem_bytes = 2 * (size_t)D * D * sizeof(float);  // 128 KB
    cudaFuncSetAttribute(gemm_hist, cudaFuncAttributeMaxDynamicSharedMemorySize,
                         (int)smem_bytes);
    gemm_hist<<<3 * GB + HIST_BLOCKS, 256, smem_bytes>>>(
        embeds, qW, kW, vW, rows, N, E, GB);

    // 3) CSR prefix sums
    int nb = (N + SCAN_ELEMS - 1) / SCAN_ELEMS;
    scan1<<<nb, 256>>>(N);
    scan23<<<nb, 256>>>(N, E);

    // 4) scatter cols into row-major edge order
    scatter_kernel<<<(E + 255) / 256, 256>>>(rows, cols, E);

    // 5) per-row attention + aggregation (register accumulation, no atomics)
    row_process<<<(N * 32 + 255) / 256, 256>>>((float4*)out, N);
}